// round 13
// baseline (speedup 1.0000x reference)
#include <cuda_runtime.h>
#include <cuda_fp16.h>

#define Nn 8
#define Hh 768
#define Ww 360
#define Dd 512
#define Cc (Ww*Nn)          // 2880 columns, c = w*8 + n
#define TAPS 257            // band: |d| <= 128
#define TAPP 272
#define PI_D 3.14159265358979323846
typedef unsigned long long ull;

// ---------------- scratch (no allocation allowed) ----------------
__device__ float g_kcp[TAPP];                // kcp[s] = k_signed(s-128), zero-padded
__device__ float g_Rb[Cc*Hh];                // x-blended radon columns, [c][y]
__device__ __align__(16) __half g_blend2[(size_t)Ww*Hh*Nn];  // filtered, [w][y][n] fp16
__device__ float g_A[Ww], g_B[Ww];
__device__ int   g_x0[Ww], g_x1[Ww];
__device__ float g_w0[Ww], g_w1[Ww];

// packed fp32x2 FMA (Blackwell)
#define FMA_F32X2(acc, d, k) asm("fma.rn.f32x2 %0, %1, %2, %0;" : "+l"(acc) : "l"(d), "l"(k))

// ---------------- stage A: banded filter taps via double DFT ----------------
__global__ void compute_kcp_kernel(const float* __restrict__ hG) {
    int m = blockIdx.x;          // 0..271
    int t = threadIdx.x;
    double acc = 0.0;
    if (m < TAPS) {
        double dd = (double)(m - 128);
        double ang = 2.0 * PI_D * dd / (double)Hh;
        for (int u = t; u < Hh; u += 256)
            acc += (double)hG[u] * cos(ang * (double)u);
    }
    __shared__ double red[256];
    red[t] = acc;
    __syncthreads();
    for (int s = 128; s > 0; s >>= 1) {
        if (t < s) red[t] += red[t + s];
        __syncthreads();
    }
    if (t == 0) g_kcp[m] = (m < TAPS) ? (float)(red[0] / (double)Hh) : 0.0f;
}

// ---------------- stage B: per-angle params (replicates reference f32 math) ----------------
__global__ void params_kernel() {
    int w = threadIdx.x;
    if (w >= Ww) return;
    float thf = __double2float_rn(PI_D / 180.0) * (0.5f * (float)w);
    double c = cos((double)thf), s = sin((double)thf);
    double sc = 383.5 / 384.0;
    g_A[w] = (float)(c * sc);
    g_B[w] = (float)(-s * sc);
    float step = __double2float_rn(2.0 / 359.0);
    float tx = -1.0f + (float)w * step;
    float px = (tx + 1.0f) * 179.5f;
    float x0f = floorf(px);
    float wx = px - x0f;
    int ix0 = (int)x0f, ix1 = ix0 + 1;
    float v0 = (ix0 >= 0 && ix0 < Ww) ? 1.0f : 0.0f;
    float v1 = (ix1 >= 0 && ix1 < Ww) ? 1.0f : 0.0f;
    g_w0[w] = (1.0f - wx) * v0;
    g_w1[w] = wx * v1;
    g_x0[w] = min(max(ix0, 0), Ww - 1);
    g_x1[w] = min(max(ix1, 0), Ww - 1);
}

// ---------------- stage C: x-blend, smem-tiled (coalesced in AND out) ----------------
__global__ void __launch_bounds__(256) rb_kernel(const float* __restrict__ radon) {
    __shared__ float sm[32 * 361];     // stride 361: conflict-free
    int n = blockIdx.y;
    int yt = blockIdx.x * 32;
    int tid = threadIdx.x;
    const float* src = radon + ((size_t)n * Hh + yt) * Ww;
#pragma unroll
    for (int idx = tid; idx < 32 * Ww; idx += 256) {
        int y = idx / Ww, x = idx - y * Ww;
        sm[y * 361 + x] = src[y * Ww + x];
    }
    __syncthreads();
#pragma unroll
    for (int idx = tid; idx < Ww * 32; idx += 256) {
        int w = idx >> 5, y = idx & 31;
        float v = sm[y * 361 + g_x0[w]] * g_w0[w] + sm[y * 361 + g_x1[w]] * g_w1[w];
        g_Rb[(size_t)(w * 8 + n) * Hh + yt + y] = v;
    }
}

// ---------------- stage D: 257-tap circular band conv (proven 35.8us, R4 version) ----------
#define SROW 66                     // words per row (32 float2 + 1 pad float2)
#define TBW 528                     // halfs per w4 slice in transpose buf
__global__ void __launch_bounds__(256) conv_kernel() {
    extern __shared__ float dyn[];
    float* s = dyn;                          // 320*66 words
    float* skc = dyn + 320 * SROW;           // 264 words
    __half* tb = (__half*)(skc + 264);       // 8*528 halfs

    int tid = threadIdx.x;
    int ctile = blockIdx.x * 64;
    int wtile = blockIdx.x * 8;
    int ytile = blockIdx.y * 64;

    for (int i = tid; i < 264; i += 256) skc[i] = g_kcp[i];

    {
        int cloc = tid >> 3;
        int uoff = tid & 7;
        const float* src0 = g_Rb + (ctile + cloc) * Hh;
        const float* src1 = g_Rb + (ctile + 32 + cloc) * Hh;
#pragma unroll
        for (int u = uoff; u < 320; u += 8) {
            int y = ytile + u - 128;
            if (y < 0) y += Hh; else if (y >= Hh) y -= Hh;
            s[u * SROW + cloc * 2]     = src0[y];
            s[u * SROW + cloc * 2 + 1] = src1[y];
        }
    }
    __syncthreads();

    int lane = tid & 31;
    int wi = tid >> 5;
    int y0 = wi << 3;

    ull a64[8] = {0,0,0,0,0,0,0,0};
    ull k2[8] = {0,0,0,0,0,0,0,0};
    const float* srow = s + y0 * SROW + lane * 2;

#pragma unroll 8
    for (int ss = 0; ss < 264; ss++) {
        ull d = *(const ull*)(srow + ss * SROW);
#pragma unroll
        for (int r = 7; r > 0; r--) k2[r] = k2[r - 1];
        {
            unsigned int ki = __float_as_uint(skc[ss]);
            ull kn;
            asm("mov.b64 %0, {%1, %1};" : "=l"(kn) : "r"(ki));
            k2[0] = kn;
        }
#pragma unroll
        for (int r = 0; r < 8; r++) FMA_F32X2(a64[r], d, k2[r]);
    }

    {
        int w4a = lane >> 3, nn = lane & 7;
        __half* pa = tb + w4a * TBW + y0 * 8 + nn;
        __half* pb = tb + (w4a + 4) * TBW + y0 * 8 + nn;
#pragma unroll
        for (int r = 0; r < 8; r++) {
            float2 f = *(float2*)&a64[r];
            pa[r * 8] = __float2half_rn(f.x);
            pb[r * 8] = __float2half_rn(f.y);
        }
    }
    __syncthreads();

#pragma unroll
    for (int rr = tid; rr < 512; rr += 256) {
        int w4 = rr >> 6, yy = rr & 63;
        uint4 v = *(uint4*)(tb + w4 * TBW + yy * 8);
        *(uint4*)(g_blend2 + ((size_t)(wtile + w4) * Hh + ytile + yy) * 8) = v;
    }
}

// ---------------- stage E: backprojection v8 — sign-general adjacent-j row sharing ----
// grid (8,16)=128 blocks, 1024 threads, tile 64j x 32i; thread: 2 ADJACENT j x 1 i x 8 batches.
// |py1-py0|=|A|<1 => floor(py0),floor(py1) differ by at most 1; rows yb..yb+2 (yb=min) cover
// both bilinear pairs: 3 LDS.128 per 2 pixels. Per-pixel pair chosen by SEL (ALU, idle pipe).
#define BP_STAGES 8
#define BP_ANG 8
#define BP_ROWS 80
#define BP_ANG_BYTES (BP_ROWS * 16)                 // 1280
#define BP_STAGE_U4 (BP_ANG * BP_ROWS)              // 640 uint4
#define BP_STAGE_BYTES (BP_STAGE_U4 * 16)           // 10240
#define BP_ROUNDS (Ww / BP_ANG)                     // 45
__global__ void __launch_bounds__(1024, 1) backproj_kernel(float* __restrict__ out) {
    extern __shared__ __align__(16) uint4 ph[];     // 8 stages x 640 uint4 = 80KB
    __shared__ float shA[Ww], shB[Ww], shYc[Ww];
    __shared__ int shY[Ww];
    __shared__ __align__(8) unsigned long long mbar[BP_STAGES];

    int tid = threadIdx.x;

    float jr0 = (float)((int)blockIdx.x * 64 - 256);
    float jr1 = jr0 + 63.0f;
    float ir0f = (float)((int)blockIdx.y * 32 - 256);
    float ir1f = ir0f + 31.0f;

    if (tid < Ww) {
        float A = g_A[tid], B = g_B[tid];
        shA[tid] = A; shB[tid] = B;
        float minpy = fminf(A * jr0, A * jr1) + fminf(B * ir0f, B * ir1f) + 383.5f;
        int ylo = (int)minpy - 2;
        ylo = min(max(ylo, 0), Hh - BP_ROWS);
        shY[tid] = ylo;
        shYc[tid] = 383.5f - (float)ylo;
    }

    unsigned int mbar_base, ph_base;
    {
        unsigned long long gp = (unsigned long long)mbar;
        asm("{ .reg .u64 t; cvta.to.shared.u64 t, %1; cvt.u32.u64 %0, t; }"
            : "=r"(mbar_base) : "l"(gp));
        gp = (unsigned long long)ph;
        asm("{ .reg .u64 t; cvta.to.shared.u64 t, %1; cvt.u32.u64 %0, t; }"
            : "=r"(ph_base) : "l"(gp));
    }

    if (tid < BP_STAGES)
        asm volatile("mbarrier.init.shared.b64 [%0], %1;"
                     :: "r"(mbar_base + tid * 8), "r"(1) : "memory");
    __syncthreads();     // shY/shA/shB/shYc + mbar init visible

    const char* gsrc = (const char*)g_blend2;
    if (tid == 0) {
#pragma unroll
        for (int s = 0; s < BP_STAGES; s++) {
            unsigned int mb = mbar_base + s * 8;
            asm volatile("mbarrier.arrive.expect_tx.shared.b64 _, [%0], %1;"
                         :: "r"(mb), "r"(BP_STAGE_BYTES) : "memory");
#pragma unroll
            for (int h = 0; h < BP_ANG; h++) {
                int a = s * BP_ANG + h;
                asm volatile("cp.async.bulk.shared::cta.global.mbarrier::complete_tx::bytes "
                             "[%0], [%1], %2, [%3];"
                             :: "r"(ph_base + s * BP_STAGE_BYTES + h * BP_ANG_BYTES),
                                "l"(gsrc + ((size_t)a * Hh + shY[a]) * 16),
                                "r"(BP_ANG_BYTES), "r"(mb) : "memory");
            }
        }
    }

    int warp = tid >> 5, lane = tid & 31;
    int li = lane & 7;                 // 8 consecutive lanes = 8 consecutive i
    int lj2 = lane >> 3;               // 4 j-pairs per warp
    int jgrp = warp & 7, igrp = warp >> 3;
    int j0 = blockIdx.x * 64 + jgrp * 8 + lj2 * 2;      // this thread: pixels j0, j0+1
    float jr = (float)(j0 - 256);
    int i = blockIdx.y * 32 + igrp * 8 + li;
    float irf = (float)(i - 256);

    float acc[2][8] = {};
    __half2 hones = __float2half2_rn(1.0f);

    for (int rnd = 0; rnd < BP_ROUNDS; rnd++) {
        int b = rnd % BP_STAGES;
        unsigned int mb = mbar_base + b * 8;
        unsigned int parity = (unsigned int)((rnd / BP_STAGES) & 1);
        {
            unsigned int done;
            asm volatile(
                "{\n\t.reg .pred p;\n\t"
                "mbarrier.try_wait.parity.shared.b64 p, [%1], %2;\n\t"
                "selp.b32 %0, 1, 0, p;\n\t}"
                : "=r"(done) : "r"(mb), "r"(parity) : "memory");
            while (!done) {
                asm volatile(
                    "{\n\t.reg .pred p;\n\t"
                    "mbarrier.try_wait.parity.shared.b64 p, [%1], %2, 0x989680;\n\t"
                    "selp.b32 %0, 1, 0, p;\n\t}"
                    : "=r"(done) : "r"(mb), "r"(parity) : "memory");
            }
        }

        const uint4* buf = ph + b * BP_STAGE_U4;

#pragma unroll
        for (int g2 = 0; g2 < 2; g2++) {       // flush half2 partials every 4 angles
            __half2 pacc0[4], pacc1[4];
#pragma unroll
            for (int q = 0; q < 4; q++) {
                pacc0[q] = __float2half2_rn(0.0f);
                pacc1[q] = __float2half2_rn(0.0f);
            }

#pragma unroll
            for (int hh = 0; hh < 4; hh++) {
                int h = g2 * 4 + hh;
                int a = BP_ANG * rnd + h;
                float A = shA[a], B = shB[a];
                float yc = shYc[a];
                const uint4* rows = buf + h * BP_ROWS;

                float py0 = fmaf(A, jr, fmaf(B, irf, yc));   // window-relative py, in [2,78)
                int y0 = (int)py0;
                float wy0 = py0 - (float)y0;
                float py1 = py0 + A;                          // |A| < 1, sign arbitrary
                int y1 = (int)py1;
                float wy1 = py1 - (float)y1;
                int yb = min(y0, y1);
                int s0 = y0 - yb;                             // 0 or 1
                int s1 = y1 - yb;                             // 0 or 1

                uint4 r0 = rows[yb];
                uint4 r1 = rows[yb + 1];
                uint4 r2 = rows[yb + 2];

                __half2 h10 = __float2half2_rn(wy0);
                __half2 h00 = __hsub2(hones, h10);
                __half2 h11 = __float2half2_rn(wy1);
                __half2 h01 = __hsub2(hones, h11);

                const unsigned int* a0 = (const unsigned int*)&r0;
                const unsigned int* a1 = (const unsigned int*)&r1;
                const unsigned int* a2 = (const unsigned int*)&r2;
#pragma unroll
                for (int q = 0; q < 4; q++) {
                    unsigned int p0a = s0 ? a1[q] : a0[q];
                    unsigned int p0b = s0 ? a2[q] : a1[q];
                    __half2 va = *(__half2*)&p0a;
                    __half2 vb = *(__half2*)&p0b;
                    pacc0[q] = __hfma2(va, h00, pacc0[q]);
                    pacc0[q] = __hfma2(vb, h10, pacc0[q]);
                    unsigned int p1a = s1 ? a1[q] : a0[q];
                    unsigned int p1b = s1 ? a2[q] : a1[q];
                    __half2 vc = *(__half2*)&p1a;
                    __half2 vd = *(__half2*)&p1b;
                    pacc1[q] = __hfma2(vc, h01, pacc1[q]);
                    pacc1[q] = __hfma2(vd, h11, pacc1[q]);
                }
            }
#pragma unroll
            for (int q = 0; q < 4; q++) {
                float2 f0 = __half22float2(pacc0[q]);
                float2 f1 = __half22float2(pacc1[q]);
                acc[0][2 * q]     += f0.x;
                acc[0][2 * q + 1] += f0.y;
                acc[1][2 * q]     += f1.x;
                acc[1][2 * q + 1] += f1.y;
            }
        }

        __syncthreads();            // all readers of stage b done
        if (tid == 0 && rnd + BP_STAGES < BP_ROUNDS) {
            asm volatile("mbarrier.arrive.expect_tx.shared.b64 _, [%0], %1;"
                         :: "r"(mb), "r"(BP_STAGE_BYTES) : "memory");
#pragma unroll
            for (int h = 0; h < BP_ANG; h++) {
                int a = (rnd + BP_STAGES) * BP_ANG + h;
                asm volatile("cp.async.bulk.shared::cta.global.mbarrier::complete_tx::bytes "
                             "[%0], [%1], %2, [%3];"
                             :: "r"(ph_base + b * BP_STAGE_BYTES + h * BP_ANG_BYTES),
                                "l"(gsrc + ((size_t)a * Hh + shY[a]) * 16),
                                "r"(BP_ANG_BYTES), "r"(mb) : "memory");
            }
        }
    }

    const float SC = (float)(PI_D / 720.0);   // pi / (2W)
#pragma unroll
    for (int p = 0; p < 2; p++) {
#pragma unroll
        for (int n = 0; n < 8; n++)
            out[n * (Dd * Dd) + i * Dd + j0 + p] = acc[p][n] * SC;
    }
}

// ---------------- launch ----------------
extern "C" void kernel_launch(void* const* d_in, const int* in_sizes, int n_in,
                              void* d_out, int out_size) {
    (void)in_sizes; (void)n_in; (void)out_size;
    const float* radon = (const float*)d_in[0];
    const float* hG    = (const float*)d_in[1];
    float* out = (float*)d_out;

    const int conv_smem = (320 * SROW + 264) * 4 + 8 * TBW * 2;   // 93,984 B
    cudaFuncSetAttribute(conv_kernel, cudaFuncAttributeMaxDynamicSharedMemorySize, conv_smem);
    const int bp_smem = BP_STAGES * BP_STAGE_BYTES;                // 81,920 B
    cudaFuncSetAttribute(backproj_kernel, cudaFuncAttributeMaxDynamicSharedMemorySize, bp_smem);

    compute_kcp_kernel<<<TAPP, 256>>>(hG);
    params_kernel<<<1, 384>>>();
    rb_kernel<<<dim3(24, 8), 256>>>(radon);
    conv_kernel<<<dim3(45, 12), 256, conv_smem>>>();
    backproj_kernel<<<dim3(8, 16), 1024, bp_smem>>>(out);
}

// round 14
// speedup vs baseline: 1.0825x; 1.0825x over previous
#include <cuda_runtime.h>
#include <cuda_fp16.h>

#define Nn 8
#define Hh 768
#define Ww 360
#define Dd 512
#define Cc (Ww*Nn)          // 2880 columns, c = w*8 + n
#define TAPS 193            // band: |d| <= 96
#define TAPP 200            // padded to multiple of 8
#define PI_D 3.14159265358979323846
typedef unsigned long long ull;

// ---------------- scratch (no allocation allowed) ----------------
__device__ float g_kcp[TAPP];                // kcp[s] = k_signed(s-96), zero-padded
__device__ float g_Rb[Cc*Hh];                // x-blended radon columns, [c][y]
__device__ __align__(16) __half g_blend2[(size_t)Ww*Hh*Nn];  // filtered, [w][y][n] fp16
__device__ float g_A[Ww], g_B[Ww];
__device__ int   g_x0[Ww], g_x1[Ww];
__device__ float g_w0[Ww], g_w1[Ww];

// packed fp32x2 FMA (Blackwell)
#define FMA_F32X2(acc, d, k) asm("fma.rn.f32x2 %0, %1, %2, %0;" : "+l"(acc) : "l"(d), "l"(k))

// ---------------- stage A: banded filter taps via double DFT ----------------
__global__ void compute_kcp_kernel(const float* __restrict__ hG) {
    int m = blockIdx.x;          // 0..199
    int t = threadIdx.x;
    double acc = 0.0;
    if (m < TAPS) {
        double dd = (double)(m - 96);
        double ang = 2.0 * PI_D * dd / (double)Hh;
        for (int u = t; u < Hh; u += 256)
            acc += (double)hG[u] * cos(ang * (double)u);
    }
    __shared__ double red[256];
    red[t] = acc;
    __syncthreads();
    for (int s = 128; s > 0; s >>= 1) {
        if (t < s) red[t] += red[t + s];
        __syncthreads();
    }
    if (t == 0) g_kcp[m] = (m < TAPS) ? (float)(red[0] / (double)Hh) : 0.0f;
}

// ---------------- stage B: per-angle params (replicates reference f32 math) ----------------
__global__ void params_kernel() {
    int w = threadIdx.x;
    if (w >= Ww) return;
    float thf = __double2float_rn(PI_D / 180.0) * (0.5f * (float)w);
    double c = cos((double)thf), s = sin((double)thf);
    double sc = 383.5 / 384.0;
    g_A[w] = (float)(c * sc);
    g_B[w] = (float)(-s * sc);
    float step = __double2float_rn(2.0 / 359.0);
    float tx = -1.0f + (float)w * step;
    float px = (tx + 1.0f) * 179.5f;
    float x0f = floorf(px);
    float wx = px - x0f;
    int ix0 = (int)x0f, ix1 = ix0 + 1;
    float v0 = (ix0 >= 0 && ix0 < Ww) ? 1.0f : 0.0f;
    float v1 = (ix1 >= 0 && ix1 < Ww) ? 1.0f : 0.0f;
    g_w0[w] = (1.0f - wx) * v0;
    g_w1[w] = wx * v1;
    g_x0[w] = min(max(ix0, 0), Ww - 1);
    g_x1[w] = min(max(ix1, 0), Ww - 1);
}

// ---------------- stage C: x-blend, smem-tiled (coalesced in AND out) ----------------
__global__ void __launch_bounds__(256) rb_kernel(const float* __restrict__ radon) {
    __shared__ float sm[32 * 361];     // stride 361: conflict-free
    int n = blockIdx.y;
    int yt = blockIdx.x * 32;
    int tid = threadIdx.x;
    const float* src = radon + ((size_t)n * Hh + yt) * Ww;
#pragma unroll
    for (int idx = tid; idx < 32 * Ww; idx += 256) {
        int y = idx / Ww, x = idx - y * Ww;
        sm[y * 361 + x] = src[y * Ww + x];
    }
    __syncthreads();
#pragma unroll
    for (int idx = tid; idx < Ww * 32; idx += 256) {
        int w = idx >> 5, y = idx & 31;
        float v = sm[y * 361 + g_x0[w]] * g_w0[w] + sm[y * 361 + g_x1[w]] * g_w1[w];
        g_Rb[(size_t)(w * 8 + n) * Hh + yt + y] = v;
    }
}

// ---------------- stage D: 193-tap circular band conv (R4 structure, +-96 band) ----------
#define SROW 66                     // words per row (32 float2 + 1 pad float2)
#define TBW 528                     // halfs per w4 slice in transpose buf
#define WIN 256                     // window rows: 64 + 2*96
__global__ void __launch_bounds__(256) conv_kernel() {
    extern __shared__ float dyn[];
    float* s = dyn;                          // 256*66 words
    float* skc = dyn + WIN * SROW;           // 200 words
    __half* tb = (__half*)(skc + TAPP);      // 8*528 halfs

    int tid = threadIdx.x;
    int ctile = blockIdx.x * 64;
    int wtile = blockIdx.x * 8;
    int ytile = blockIdx.y * 64;

    for (int i = tid; i < TAPP; i += 256) skc[i] = g_kcp[i];

    {
        int cloc = tid >> 3;
        int uoff = tid & 7;
        const float* src0 = g_Rb + (ctile + cloc) * Hh;
        const float* src1 = g_Rb + (ctile + 32 + cloc) * Hh;
#pragma unroll
        for (int u = uoff; u < WIN; u += 8) {
            int y = ytile + u - 96;
            if (y < 0) y += Hh; else if (y >= Hh) y -= Hh;
            s[u * SROW + cloc * 2]     = src0[y];
            s[u * SROW + cloc * 2 + 1] = src1[y];
        }
    }
    __syncthreads();

    int lane = tid & 31;
    int wi = tid >> 5;
    int y0 = wi << 3;

    ull a64[8] = {0,0,0,0,0,0,0,0};
    ull k2[8] = {0,0,0,0,0,0,0,0};
    const float* srow = s + y0 * SROW + lane * 2;

#pragma unroll 8
    for (int ss = 0; ss < TAPP; ss++) {
        ull d = *(const ull*)(srow + ss * SROW);
#pragma unroll
        for (int r = 7; r > 0; r--) k2[r] = k2[r - 1];
        {
            unsigned int ki = __float_as_uint(skc[ss]);
            ull kn;
            asm("mov.b64 %0, {%1, %1};" : "=l"(kn) : "r"(ki));
            k2[0] = kn;
        }
#pragma unroll
        for (int r = 0; r < 8; r++) FMA_F32X2(a64[r], d, k2[r]);
    }

    {
        int w4a = lane >> 3, nn = lane & 7;
        __half* pa = tb + w4a * TBW + y0 * 8 + nn;
        __half* pb = tb + (w4a + 4) * TBW + y0 * 8 + nn;
#pragma unroll
        for (int r = 0; r < 8; r++) {
            float2 f = *(float2*)&a64[r];
            pa[r * 8] = __float2half_rn(f.x);
            pb[r * 8] = __float2half_rn(f.y);
        }
    }
    __syncthreads();

#pragma unroll
    for (int rr = tid; rr < 512; rr += 256) {
        int w4 = rr >> 6, yy = rr & 63;
        uint4 v = *(uint4*)(tb + w4 * TBW + yy * 8);
        *(uint4*)(g_blend2 + ((size_t)(wtile + w4) * Hh + ytile + yy) * 8) = v;
    }
}

// ---------------- stage E: backprojection v9 — full-chip tiling, proven v8 inner loop ----
// grid (16,64)=1024 blocks, 128 threads (4 warps), 8 blocks/SM. Tile 32j x 8i; thread:
// 2 ADJACENT j x 1 i x 8 batches. 4 TMA stages x 8 angles x 40-row windows (20.5KB).
#define BP_STAGES 4
#define BP_ANG 8
#define BP_ROWS 40
#define BP_ANG_BYTES (BP_ROWS * 16)                 // 640
#define BP_STAGE_U4 (BP_ANG * BP_ROWS)              // 320 uint4
#define BP_STAGE_BYTES (BP_STAGE_U4 * 16)           // 5120
#define BP_ROUNDS (Ww / BP_ANG)                     // 45
__global__ void __launch_bounds__(128, 8) backproj_kernel(float* __restrict__ out) {
    extern __shared__ __align__(16) uint4 ph[];     // 4 stages x 320 uint4 = 20480 B
    __shared__ float shA[Ww], shB[Ww], shYc[Ww];
    __shared__ int shY[Ww];
    __shared__ __align__(8) unsigned long long mbar[BP_STAGES];

    int tid = threadIdx.x;

    float jr0 = (float)((int)blockIdx.x * 32 - 256);
    float jr1 = jr0 + 31.0f;
    float ir0f = (float)((int)blockIdx.y * 8 - 256);
    float ir1f = ir0f + 7.0f;

    for (int idx = tid; idx < Ww; idx += 128) {
        float A = g_A[idx], B = g_B[idx];
        shA[idx] = A; shB[idx] = B;
        float minpy = fminf(A * jr0, A * jr1) + fminf(B * ir0f, B * ir1f) + 383.5f;
        int ylo = (int)minpy - 2;
        ylo = min(max(ylo, 0), Hh - BP_ROWS);
        shY[idx] = ylo;
        shYc[idx] = 383.5f - (float)ylo;
    }

    unsigned int mbar_base, ph_base;
    {
        unsigned long long gp = (unsigned long long)mbar;
        asm("{ .reg .u64 t; cvta.to.shared.u64 t, %1; cvt.u32.u64 %0, t; }"
            : "=r"(mbar_base) : "l"(gp));
        gp = (unsigned long long)ph;
        asm("{ .reg .u64 t; cvta.to.shared.u64 t, %1; cvt.u32.u64 %0, t; }"
            : "=r"(ph_base) : "l"(gp));
    }

    if (tid < BP_STAGES)
        asm volatile("mbarrier.init.shared.b64 [%0], %1;"
                     :: "r"(mbar_base + tid * 8), "r"(1) : "memory");
    __syncthreads();     // shY/shA/shB/shYc + mbar init visible

    const char* gsrc = (const char*)g_blend2;
    if (tid == 0) {
#pragma unroll
        for (int s = 0; s < BP_STAGES; s++) {
            unsigned int mb = mbar_base + s * 8;
            asm volatile("mbarrier.arrive.expect_tx.shared.b64 _, [%0], %1;"
                         :: "r"(mb), "r"(BP_STAGE_BYTES) : "memory");
#pragma unroll
            for (int h = 0; h < BP_ANG; h++) {
                int a = s * BP_ANG + h;
                asm volatile("cp.async.bulk.shared::cta.global.mbarrier::complete_tx::bytes "
                             "[%0], [%1], %2, [%3];"
                             :: "r"(ph_base + s * BP_STAGE_BYTES + h * BP_ANG_BYTES),
                                "l"(gsrc + ((size_t)a * Hh + shY[a]) * 16),
                                "r"(BP_ANG_BYTES), "r"(mb) : "memory");
            }
        }
    }

    int warp = tid >> 5, lane = tid & 31;
    int li = lane & 7;                 // 8 consecutive lanes = 8 consecutive i
    int lj2 = lane >> 3;               // 4 j-pairs per warp
    int j0 = blockIdx.x * 32 + warp * 8 + lj2 * 2;      // this thread: pixels j0, j0+1
    float jr = (float)(j0 - 256);
    int i = blockIdx.y * 8 + li;
    float irf = (float)(i - 256);

    float acc[2][8] = {};
    __half2 hones = __float2half2_rn(1.0f);

    for (int rnd = 0; rnd < BP_ROUNDS; rnd++) {
        int b = rnd % BP_STAGES;
        unsigned int mb = mbar_base + b * 8;
        unsigned int parity = (unsigned int)((rnd / BP_STAGES) & 1);
        {
            unsigned int done;
            asm volatile(
                "{\n\t.reg .pred p;\n\t"
                "mbarrier.try_wait.parity.shared.b64 p, [%1], %2;\n\t"
                "selp.b32 %0, 1, 0, p;\n\t}"
                : "=r"(done) : "r"(mb), "r"(parity) : "memory");
            while (!done) {
                asm volatile(
                    "{\n\t.reg .pred p;\n\t"
                    "mbarrier.try_wait.parity.shared.b64 p, [%1], %2, 0x989680;\n\t"
                    "selp.b32 %0, 1, 0, p;\n\t}"
                    : "=r"(done) : "r"(mb), "r"(parity) : "memory");
            }
        }

        const uint4* buf = ph + b * BP_STAGE_U4;

#pragma unroll
        for (int g2 = 0; g2 < 2; g2++) {       // flush half2 partials every 4 angles
            __half2 pacc0[4], pacc1[4];
#pragma unroll
            for (int q = 0; q < 4; q++) {
                pacc0[q] = __float2half2_rn(0.0f);
                pacc1[q] = __float2half2_rn(0.0f);
            }

#pragma unroll
            for (int hh = 0; hh < 4; hh++) {
                int h = g2 * 4 + hh;
                int a = BP_ANG * rnd + h;
                float A = shA[a], B = shB[a];
                float yc = shYc[a];
                const uint4* rows = buf + h * BP_ROWS;

                float py0 = fmaf(A, jr, fmaf(B, irf, yc));   // window-relative py
                int y0 = (int)py0;
                float wy0 = py0 - (float)y0;
                float py1 = py0 + A;                          // |A| < 1, sign arbitrary
                int y1 = (int)py1;
                float wy1 = py1 - (float)y1;
                int yb = min(y0, y1);
                int s0 = y0 - yb;                             // 0 or 1
                int s1 = y1 - yb;                             // 0 or 1

                uint4 r0 = rows[yb];
                uint4 r1 = rows[yb + 1];
                uint4 r2 = rows[yb + 2];

                __half2 h10 = __float2half2_rn(wy0);
                __half2 h00 = __hsub2(hones, h10);
                __half2 h11 = __float2half2_rn(wy1);
                __half2 h01 = __hsub2(hones, h11);

                const unsigned int* a0 = (const unsigned int*)&r0;
                const unsigned int* a1 = (const unsigned int*)&r1;
                const unsigned int* a2 = (const unsigned int*)&r2;
#pragma unroll
                for (int q = 0; q < 4; q++) {
                    unsigned int p0a = s0 ? a1[q] : a0[q];
                    unsigned int p0b = s0 ? a2[q] : a1[q];
                    __half2 va = *(__half2*)&p0a;
                    __half2 vb = *(__half2*)&p0b;
                    pacc0[q] = __hfma2(va, h00, pacc0[q]);
                    pacc0[q] = __hfma2(vb, h10, pacc0[q]);
                    unsigned int p1a = s1 ? a1[q] : a0[q];
                    unsigned int p1b = s1 ? a2[q] : a1[q];
                    __half2 vc = *(__half2*)&p1a;
                    __half2 vd = *(__half2*)&p1b;
                    pacc1[q] = __hfma2(vc, h01, pacc1[q]);
                    pacc1[q] = __hfma2(vd, h11, pacc1[q]);
                }
            }
#pragma unroll
            for (int q = 0; q < 4; q++) {
                float2 f0 = __half22float2(pacc0[q]);
                float2 f1 = __half22float2(pacc1[q]);
                acc[0][2 * q]     += f0.x;
                acc[0][2 * q + 1] += f0.y;
                acc[1][2 * q]     += f1.x;
                acc[1][2 * q + 1] += f1.y;
            }
        }

        __syncthreads();            // all readers of stage b done
        if (tid == 0 && rnd + BP_STAGES < BP_ROUNDS) {
            asm volatile("mbarrier.arrive.expect_tx.shared.b64 _, [%0], %1;"
                         :: "r"(mb), "r"(BP_STAGE_BYTES) : "memory");
#pragma unroll
            for (int h = 0; h < BP_ANG; h++) {
                int a = (rnd + BP_STAGES) * BP_ANG + h;
                asm volatile("cp.async.bulk.shared::cta.global.mbarrier::complete_tx::bytes "
                             "[%0], [%1], %2, [%3];"
                             :: "r"(ph_base + b * BP_STAGE_BYTES + h * BP_ANG_BYTES),
                                "l"(gsrc + ((size_t)a * Hh + shY[a]) * 16),
                                "r"(BP_ANG_BYTES), "r"(mb) : "memory");
            }
        }
    }

    const float SC = (float)(PI_D / 720.0);   // pi / (2W)
#pragma unroll
    for (int p = 0; p < 2; p++) {
#pragma unroll
        for (int n = 0; n < 8; n++)
            out[n * (Dd * Dd) + i * Dd + j0 + p] = acc[p][n] * SC;
    }
}

// ---------------- launch ----------------
extern "C" void kernel_launch(void* const* d_in, const int* in_sizes, int n_in,
                              void* d_out, int out_size) {
    (void)in_sizes; (void)n_in; (void)out_size;
    const float* radon = (const float*)d_in[0];
    const float* hG    = (const float*)d_in[1];
    float* out = (float*)d_out;

    const int conv_smem = (WIN * SROW + TAPP) * 4 + 8 * TBW * 2;  // 76,832 B
    cudaFuncSetAttribute(conv_kernel, cudaFuncAttributeMaxDynamicSharedMemorySize, conv_smem);
    const int bp_smem = BP_STAGES * BP_STAGE_BYTES;                // 20,480 B
    cudaFuncSetAttribute(backproj_kernel, cudaFuncAttributeMaxDynamicSharedMemorySize, bp_smem);

    compute_kcp_kernel<<<TAPP, 256>>>(hG);
    params_kernel<<<1, 384>>>();
    rb_kernel<<<dim3(24, 8), 256>>>(radon);
    conv_kernel<<<dim3(45, 12), 256, conv_smem>>>();
    backproj_kernel<<<dim3(16, 64), 128, bp_smem>>>(out);
}

// round 15
// speedup vs baseline: 1.1129x; 1.0281x over previous
#include <cuda_runtime.h>
#include <cuda_fp16.h>

#define Nn 8
#define Hh 768
#define Ww 360
#define Dd 512
#define Cc (Ww*Nn)          // 2880 columns, c = w*8 + n
#define TAPS 193            // band: |d| <= 96
#define TAPP 200            // padded to multiple of 8
#define PI_D 3.14159265358979323846
typedef unsigned long long ull;

// ---------------- scratch (no allocation allowed) ----------------
__device__ float g_kcp[TAPP];                // kcp[s] = k_signed(s-96), zero-padded
__device__ float g_Rb[Cc*Hh];                // x-blended radon columns, [c][y]
__device__ __align__(16) __half g_blend2[(size_t)Ww*Hh*Nn];  // filtered, [w][y][n] fp16
__device__ float g_A[Ww], g_B[Ww];
__device__ int   g_x0[Ww], g_x1[Ww];
__device__ float g_w0[Ww], g_w1[Ww];

// packed fp32x2 FMA (Blackwell)
#define FMA_F32X2(acc, d, k) asm("fma.rn.f32x2 %0, %1, %2, %0;" : "+l"(acc) : "l"(d), "l"(k))

// ---------------- stage A: banded filter taps via double DFT ----------------
__global__ void compute_kcp_kernel(const float* __restrict__ hG) {
    int m = blockIdx.x;          // 0..199
    int t = threadIdx.x;
    double acc = 0.0;
    if (m < TAPS) {
        double dd = (double)(m - 96);
        double ang = 2.0 * PI_D * dd / (double)Hh;
        for (int u = t; u < Hh; u += 256)
            acc += (double)hG[u] * cos(ang * (double)u);
    }
    __shared__ double red[256];
    red[t] = acc;
    __syncthreads();
    for (int s = 128; s > 0; s >>= 1) {
        if (t < s) red[t] += red[t + s];
        __syncthreads();
    }
    if (t == 0) g_kcp[m] = (m < TAPS) ? (float)(red[0] / (double)Hh) : 0.0f;
}

// ---------------- stage B: per-angle params (replicates reference f32 math) ----------------
__global__ void params_kernel() {
    int w = threadIdx.x;
    if (w >= Ww) return;
    float thf = __double2float_rn(PI_D / 180.0) * (0.5f * (float)w);
    double c = cos((double)thf), s = sin((double)thf);
    double sc = 383.5 / 384.0;
    g_A[w] = (float)(c * sc);
    g_B[w] = (float)(-s * sc);
    float step = __double2float_rn(2.0 / 359.0);
    float tx = -1.0f + (float)w * step;
    float px = (tx + 1.0f) * 179.5f;
    float x0f = floorf(px);
    float wx = px - x0f;
    int ix0 = (int)x0f, ix1 = ix0 + 1;
    float v0 = (ix0 >= 0 && ix0 < Ww) ? 1.0f : 0.0f;
    float v1 = (ix1 >= 0 && ix1 < Ww) ? 1.0f : 0.0f;
    g_w0[w] = (1.0f - wx) * v0;
    g_w1[w] = wx * v1;
    g_x0[w] = min(max(ix0, 0), Ww - 1);
    g_x1[w] = min(max(ix1, 0), Ww - 1);
}

// ---------------- stage C: x-blend, smem-tiled (coalesced in AND out) ----------------
__global__ void __launch_bounds__(256) rb_kernel(const float* __restrict__ radon) {
    __shared__ float sm[32 * 361];     // stride 361: conflict-free
    int n = blockIdx.y;
    int yt = blockIdx.x * 32;
    int tid = threadIdx.x;
    const float* src = radon + ((size_t)n * Hh + yt) * Ww;
#pragma unroll
    for (int idx = tid; idx < 32 * Ww; idx += 256) {
        int y = idx / Ww, x = idx - y * Ww;
        sm[y * 361 + x] = src[y * Ww + x];
    }
    __syncthreads();
#pragma unroll
    for (int idx = tid; idx < Ww * 32; idx += 256) {
        int w = idx >> 5, y = idx & 31;
        float v = sm[y * 361 + g_x0[w]] * g_w0[w] + sm[y * 361 + g_x1[w]] * g_w1[w];
        g_Rb[(size_t)(w * 8 + n) * Hh + yt + y] = v;
    }
}

// ---------------- stage D: 193-tap band conv, one-wave tiling (64c x 128y, 512 thr) ----
// 270 blocks, 2/SM => single wave, 32 warps/SM. tb aliased into window (post-sync reuse).
#define SROW 66                     // words per row (32 float2 + 1 pad float2)
#define WIN 320                     // window rows: 128 + 2*96
#define TBW 1040                    // halfs per w4 slice: 128*8 + 16 pad
__global__ void __launch_bounds__(512, 2) conv_kernel() {
    extern __shared__ float dyn[];
    float* s = dyn;                          // 320*66 words = 84480 B (window)
    ull* skc2 = (ull*)(dyn + WIN * SROW);    // 200 dup'd tap pairs = 1600 B
    __half* tb = (__half*)dyn;               // transpose buf ALIASES window (8*1040*2=16640B)

    int tid = threadIdx.x;
    int ctile = blockIdx.x * 64;
    int wtile = blockIdx.x * 8;
    int ytile = blockIdx.y * 128;

    for (int i = tid; i < TAPP; i += 512) {
        unsigned int ki = __float_as_uint(g_kcp[i]);
        ull kn;
        asm("mov.b64 %0, {%1, %1};" : "=l"(kn) : "r"(ki));
        skc2[i] = kn;
    }

    {   // load window (circular wrap): 320 rows x 32 col-pairs
        int cloc = tid >> 4;          // 0..31
        int uoff = tid & 15;
        const float* src0 = g_Rb + (ctile + cloc) * Hh;
        const float* src1 = g_Rb + (ctile + 32 + cloc) * Hh;
#pragma unroll
        for (int u = uoff; u < WIN; u += 16) {
            int y = ytile + u - 96;
            if (y < 0) y += Hh; else if (y >= Hh) y -= Hh;
            s[u * SROW + cloc * 2]     = src0[y];
            s[u * SROW + cloc * 2 + 1] = src1[y];
        }
    }
    __syncthreads();

    int lane = tid & 31;
    int wi = tid >> 5;             // 0..15
    int y0 = wi << 3;              // 8 y per thread, 128 y per block

    ull a64[8] = {0,0,0,0,0,0,0,0};
    ull k2[8] = {0,0,0,0,0,0,0,0};
    const float* srow = s + y0 * SROW + lane * 2;

#pragma unroll 8
    for (int ss = 0; ss < TAPP; ss++) {
        ull d = *(const ull*)(srow + ss * SROW);
#pragma unroll
        for (int r = 7; r > 0; r--) k2[r] = k2[r - 1];
        k2[0] = skc2[ss];
#pragma unroll
        for (int r = 0; r < 8; r++) FMA_F32X2(a64[r], d, k2[r]);
    }
    __syncthreads();               // all window reads done; tb may now overwrite it

    {   // transpose to [w4][y][n] halfs in smem
        int w4a = lane >> 3, nn = lane & 7;
        __half* pa = tb + w4a * TBW + y0 * 8 + nn;
        __half* pb = tb + (w4a + 4) * TBW + y0 * 8 + nn;
#pragma unroll
        for (int r = 0; r < 8; r++) {
            float2 f = *(float2*)&a64[r];
            pa[r * 8] = __float2half_rn(f.x);
            pb[r * 8] = __float2half_rn(f.y);
        }
    }
    __syncthreads();

#pragma unroll
    for (int rr = tid; rr < 1024; rr += 512) {
        int w4 = rr >> 7, yy = rr & 127;
        uint4 v = *(uint4*)(tb + w4 * TBW + yy * 8);
        *(uint4*)(g_blend2 + ((size_t)(wtile + w4) * Hh + ytile + yy) * 8) = v;
    }
}

// ---------------- stage E: backprojection v9 (proven R14) — full-chip tiling ----
// grid (16,64)=1024 blocks, 128 threads (4 warps), 8 blocks/SM. Tile 32j x 8i; thread:
// 2 ADJACENT j x 1 i x 8 batches. 4 TMA stages x 8 angles x 40-row windows (20.5KB).
#define BP_STAGES 4
#define BP_ANG 8
#define BP_ROWS 40
#define BP_ANG_BYTES (BP_ROWS * 16)                 // 640
#define BP_STAGE_U4 (BP_ANG * BP_ROWS)              // 320 uint4
#define BP_STAGE_BYTES (BP_STAGE_U4 * 16)           // 5120
#define BP_ROUNDS (Ww / BP_ANG)                     // 45
__global__ void __launch_bounds__(128, 8) backproj_kernel(float* __restrict__ out) {
    extern __shared__ __align__(16) uint4 ph[];     // 4 stages x 320 uint4 = 20480 B
    __shared__ float shA[Ww], shB[Ww], shYc[Ww];
    __shared__ int shY[Ww];
    __shared__ __align__(8) unsigned long long mbar[BP_STAGES];

    int tid = threadIdx.x;

    float jr0 = (float)((int)blockIdx.x * 32 - 256);
    float jr1 = jr0 + 31.0f;
    float ir0f = (float)((int)blockIdx.y * 8 - 256);
    float ir1f = ir0f + 7.0f;

    for (int idx = tid; idx < Ww; idx += 128) {
        float A = g_A[idx], B = g_B[idx];
        shA[idx] = A; shB[idx] = B;
        float minpy = fminf(A * jr0, A * jr1) + fminf(B * ir0f, B * ir1f) + 383.5f;
        int ylo = (int)minpy - 2;
        ylo = min(max(ylo, 0), Hh - BP_ROWS);
        shY[idx] = ylo;
        shYc[idx] = 383.5f - (float)ylo;
    }

    unsigned int mbar_base, ph_base;
    {
        unsigned long long gp = (unsigned long long)mbar;
        asm("{ .reg .u64 t; cvta.to.shared.u64 t, %1; cvt.u32.u64 %0, t; }"
            : "=r"(mbar_base) : "l"(gp));
        gp = (unsigned long long)ph;
        asm("{ .reg .u64 t; cvta.to.shared.u64 t, %1; cvt.u32.u64 %0, t; }"
            : "=r"(ph_base) : "l"(gp));
    }

    if (tid < BP_STAGES)
        asm volatile("mbarrier.init.shared.b64 [%0], %1;"
                     :: "r"(mbar_base + tid * 8), "r"(1) : "memory");
    __syncthreads();     // shY/shA/shB/shYc + mbar init visible

    const char* gsrc = (const char*)g_blend2;
    if (tid == 0) {
#pragma unroll
        for (int s = 0; s < BP_STAGES; s++) {
            unsigned int mb = mbar_base + s * 8;
            asm volatile("mbarrier.arrive.expect_tx.shared.b64 _, [%0], %1;"
                         :: "r"(mb), "r"(BP_STAGE_BYTES) : "memory");
#pragma unroll
            for (int h = 0; h < BP_ANG; h++) {
                int a = s * BP_ANG + h;
                asm volatile("cp.async.bulk.shared::cta.global.mbarrier::complete_tx::bytes "
                             "[%0], [%1], %2, [%3];"
                             :: "r"(ph_base + s * BP_STAGE_BYTES + h * BP_ANG_BYTES),
                                "l"(gsrc + ((size_t)a * Hh + shY[a]) * 16),
                                "r"(BP_ANG_BYTES), "r"(mb) : "memory");
            }
        }
    }

    int warp = tid >> 5, lane = tid & 31;
    int li = lane & 7;                 // 8 consecutive lanes = 8 consecutive i
    int lj2 = lane >> 3;               // 4 j-pairs per warp
    int j0 = blockIdx.x * 32 + warp * 8 + lj2 * 2;      // this thread: pixels j0, j0+1
    float jr = (float)(j0 - 256);
    int i = blockIdx.y * 8 + li;
    float irf = (float)(i - 256);

    float acc[2][8] = {};
    __half2 hones = __float2half2_rn(1.0f);

    for (int rnd = 0; rnd < BP_ROUNDS; rnd++) {
        int b = rnd % BP_STAGES;
        unsigned int mb = mbar_base + b * 8;
        unsigned int parity = (unsigned int)((rnd / BP_STAGES) & 1);
        {
            unsigned int done;
            asm volatile(
                "{\n\t.reg .pred p;\n\t"
                "mbarrier.try_wait.parity.shared.b64 p, [%1], %2;\n\t"
                "selp.b32 %0, 1, 0, p;\n\t}"
                : "=r"(done) : "r"(mb), "r"(parity) : "memory");
            while (!done) {
                asm volatile(
                    "{\n\t.reg .pred p;\n\t"
                    "mbarrier.try_wait.parity.shared.b64 p, [%1], %2, 0x989680;\n\t"
                    "selp.b32 %0, 1, 0, p;\n\t}"
                    : "=r"(done) : "r"(mb), "r"(parity) : "memory");
            }
        }

        const uint4* buf = ph + b * BP_STAGE_U4;

#pragma unroll
        for (int g2 = 0; g2 < 2; g2++) {       // flush half2 partials every 4 angles
            __half2 pacc0[4], pacc1[4];
#pragma unroll
            for (int q = 0; q < 4; q++) {
                pacc0[q] = __float2half2_rn(0.0f);
                pacc1[q] = __float2half2_rn(0.0f);
            }

#pragma unroll
            for (int hh = 0; hh < 4; hh++) {
                int h = g2 * 4 + hh;
                int a = BP_ANG * rnd + h;
                float A = shA[a], B = shB[a];
                float yc = shYc[a];
                const uint4* rows = buf + h * BP_ROWS;

                float py0 = fmaf(A, jr, fmaf(B, irf, yc));   // window-relative py
                int y0 = (int)py0;
                float wy0 = py0 - (float)y0;
                float py1 = py0 + A;                          // |A| < 1, sign arbitrary
                int y1 = (int)py1;
                float wy1 = py1 - (float)y1;
                int yb = min(y0, y1);
                int s0 = y0 - yb;                             // 0 or 1
                int s1 = y1 - yb;                             // 0 or 1

                uint4 r0 = rows[yb];
                uint4 r1 = rows[yb + 1];
                uint4 r2 = rows[yb + 2];

                __half2 h10 = __float2half2_rn(wy0);
                __half2 h00 = __hsub2(hones, h10);
                __half2 h11 = __float2half2_rn(wy1);
                __half2 h01 = __hsub2(hones, h11);

                const unsigned int* a0 = (const unsigned int*)&r0;
                const unsigned int* a1 = (const unsigned int*)&r1;
                const unsigned int* a2 = (const unsigned int*)&r2;
#pragma unroll
                for (int q = 0; q < 4; q++) {
                    unsigned int p0a = s0 ? a1[q] : a0[q];
                    unsigned int p0b = s0 ? a2[q] : a1[q];
                    __half2 va = *(__half2*)&p0a;
                    __half2 vb = *(__half2*)&p0b;
                    pacc0[q] = __hfma2(va, h00, pacc0[q]);
                    pacc0[q] = __hfma2(vb, h10, pacc0[q]);
                    unsigned int p1a = s1 ? a1[q] : a0[q];
                    unsigned int p1b = s1 ? a2[q] : a1[q];
                    __half2 vc = *(__half2*)&p1a;
                    __half2 vd = *(__half2*)&p1b;
                    pacc1[q] = __hfma2(vc, h01, pacc1[q]);
                    pacc1[q] = __hfma2(vd, h11, pacc1[q]);
                }
            }
#pragma unroll
            for (int q = 0; q < 4; q++) {
                float2 f0 = __half22float2(pacc0[q]);
                float2 f1 = __half22float2(pacc1[q]);
                acc[0][2 * q]     += f0.x;
                acc[0][2 * q + 1] += f0.y;
                acc[1][2 * q]     += f1.x;
                acc[1][2 * q + 1] += f1.y;
            }
        }

        __syncthreads();            // all readers of stage b done
        if (tid == 0 && rnd + BP_STAGES < BP_ROUNDS) {
            asm volatile("mbarrier.arrive.expect_tx.shared.b64 _, [%0], %1;"
                         :: "r"(mb), "r"(BP_STAGE_BYTES) : "memory");
#pragma unroll
            for (int h = 0; h < BP_ANG; h++) {
                int a = (rnd + BP_STAGES) * BP_ANG + h;
                asm volatile("cp.async.bulk.shared::cta.global.mbarrier::complete_tx::bytes "
                             "[%0], [%1], %2, [%3];"
                             :: "r"(ph_base + b * BP_STAGE_BYTES + h * BP_ANG_BYTES),
                                "l"(gsrc + ((size_t)a * Hh + shY[a]) * 16),
                                "r"(BP_ANG_BYTES), "r"(mb) : "memory");
            }
        }
    }

    const float SC = (float)(PI_D / 720.0);   // pi / (2W)
#pragma unroll
    for (int p = 0; p < 2; p++) {
#pragma unroll
        for (int n = 0; n < 8; n++)
            out[n * (Dd * Dd) + i * Dd + j0 + p] = acc[p][n] * SC;
    }
}

// ---------------- launch ----------------
extern "C" void kernel_launch(void* const* d_in, const int* in_sizes, int n_in,
                              void* d_out, int out_size) {
    (void)in_sizes; (void)n_in; (void)out_size;
    const float* radon = (const float*)d_in[0];
    const float* hG    = (const float*)d_in[1];
    float* out = (float*)d_out;

    const int conv_smem = WIN * SROW * 4 + TAPP * 8;              // 86,080 B
    cudaFuncSetAttribute(conv_kernel, cudaFuncAttributeMaxDynamicSharedMemorySize, conv_smem);
    const int bp_smem = BP_STAGES * BP_STAGE_BYTES;                // 20,480 B
    cudaFuncSetAttribute(backproj_kernel, cudaFuncAttributeMaxDynamicSharedMemorySize, bp_smem);

    compute_kcp_kernel<<<TAPP, 256>>>(hG);
    params_kernel<<<1, 384>>>();
    rb_kernel<<<dim3(24, 8), 256>>>(radon);
    conv_kernel<<<dim3(45, 6), 512, conv_smem>>>();
    backproj_kernel<<<dim3(16, 64), 128, bp_smem>>>(out);
}

// round 16
// speedup vs baseline: 1.1673x; 1.0488x over previous
#include <cuda_runtime.h>
#include <cuda_fp16.h>

#define Nn 8
#define Hh 768
#define Ww 360
#define Dd 512
#define Cc (Ww*Nn)          // 2880 columns, c = w*8 + n
#define TAPS 169            // band: |d| <= 84
#define TAPP 176            // padded to multiple of 8
#define KOFF 84
#define PI_D 3.14159265358979323846
typedef unsigned long long ull;

// ---------------- scratch (no allocation allowed) ----------------
__device__ float g_kcp[TAPP];                // kcp[s] = k_signed(s-84), zero-padded
__device__ float g_Rb[Cc*Hh];                // x-blended radon columns, [c][y]
__device__ __align__(16) __half g_blend2[(size_t)Ww*Hh*Nn];  // filtered, [w][y][n] fp16
__device__ float g_A[Ww], g_B[Ww];
__device__ int   g_x0[Ww], g_x1[Ww];
__device__ float g_w0[Ww], g_w1[Ww];

// packed fp32x2 FMA (Blackwell)
#define FMA_F32X2(acc, d, k) asm("fma.rn.f32x2 %0, %1, %2, %0;" : "+l"(acc) : "l"(d), "l"(k))

// ---------------- stage A: banded filter taps via double DFT ----------------
__global__ void compute_kcp_kernel(const float* __restrict__ hG) {
    int m = blockIdx.x;          // 0..175
    int t = threadIdx.x;
    double acc = 0.0;
    if (m < TAPS) {
        double dd = (double)(m - KOFF);
        double ang = 2.0 * PI_D * dd / (double)Hh;
        for (int u = t; u < Hh; u += 256)
            acc += (double)hG[u] * cos(ang * (double)u);
    }
    __shared__ double red[256];
    red[t] = acc;
    __syncthreads();
    for (int s = 128; s > 0; s >>= 1) {
        if (t < s) red[t] += red[t + s];
        __syncthreads();
    }
    if (t == 0) g_kcp[m] = (m < TAPS) ? (float)(red[0] / (double)Hh) : 0.0f;
}

// ---------------- stage B: per-angle params (replicates reference f32 math) ----------------
__global__ void params_kernel() {
    int w = threadIdx.x;
    if (w >= Ww) return;
    float thf = __double2float_rn(PI_D / 180.0) * (0.5f * (float)w);
    double c = cos((double)thf), s = sin((double)thf);
    double sc = 383.5 / 384.0;
    g_A[w] = (float)(c * sc);
    g_B[w] = (float)(-s * sc);
    float step = __double2float_rn(2.0 / 359.0);
    float tx = -1.0f + (float)w * step;
    float px = (tx + 1.0f) * 179.5f;
    float x0f = floorf(px);
    float wx = px - x0f;
    int ix0 = (int)x0f, ix1 = ix0 + 1;
    float v0 = (ix0 >= 0 && ix0 < Ww) ? 1.0f : 0.0f;
    float v1 = (ix1 >= 0 && ix1 < Ww) ? 1.0f : 0.0f;
    g_w0[w] = (1.0f - wx) * v0;
    g_w1[w] = wx * v1;
    g_x0[w] = min(max(ix0, 0), Ww - 1);
    g_x1[w] = min(max(ix1, 0), Ww - 1);
}

// ---------------- stage C: x-blend, smem-tiled (coalesced in AND out) ----------------
__global__ void __launch_bounds__(256) rb_kernel(const float* __restrict__ radon) {
    __shared__ float sm[32 * 361];     // stride 361: conflict-free
    int n = blockIdx.y;
    int yt = blockIdx.x * 32;
    int tid = threadIdx.x;
    const float* src = radon + ((size_t)n * Hh + yt) * Ww;
#pragma unroll
    for (int idx = tid; idx < 32 * Ww; idx += 256) {
        int y = idx / Ww, x = idx - y * Ww;
        sm[y * 361 + x] = src[y * Ww + x];
    }
    __syncthreads();
#pragma unroll
    for (int idx = tid; idx < Ww * 32; idx += 256) {
        int w = idx >> 5, y = idx & 31;
        float v = sm[y * 361 + g_x0[w]] * g_w0[w] + sm[y * 361 + g_x1[w]] * g_w1[w];
        g_Rb[(size_t)(w * 8 + n) * Hh + yt + y] = v;
    }
}

// ---------------- stage D: 169-tap band conv, one-wave tiling (64c x 128y, 512 thr) ----
#define SROW 66                     // words per row (32 float2 + 1 pad float2)
#define WIN 296                     // window rows: 128 + 2*84
#define TBW 1040                    // halfs per w4 slice: 128*8 + 16 pad
__global__ void __launch_bounds__(512, 2) conv_kernel() {
    extern __shared__ float dyn[];
    float* s = dyn;                          // 296*66 words = 78144 B (window)
    ull* skc2 = (ull*)(dyn + WIN * SROW);    // 176 dup'd tap pairs = 1408 B
    __half* tb = (__half*)dyn;               // transpose buf ALIASES window (post-sync)

    int tid = threadIdx.x;
    int ctile = blockIdx.x * 64;
    int wtile = blockIdx.x * 8;
    int ytile = blockIdx.y * 128;

    for (int i = tid; i < TAPP; i += 512) {
        unsigned int ki = __float_as_uint(g_kcp[i]);
        ull kn;
        asm("mov.b64 %0, {%1, %1};" : "=l"(kn) : "r"(ki));
        skc2[i] = kn;
    }

    {   // load window (circular wrap): 296 rows x 32 col-pairs
        int cloc = tid >> 4;          // 0..31
        int uoff = tid & 15;
        const float* src0 = g_Rb + (ctile + cloc) * Hh;
        const float* src1 = g_Rb + (ctile + 32 + cloc) * Hh;
        for (int u = uoff; u < WIN; u += 16) {
            int y = ytile + u - KOFF;
            if (y < 0) y += Hh; else if (y >= Hh) y -= Hh;
            s[u * SROW + cloc * 2]     = src0[y];
            s[u * SROW + cloc * 2 + 1] = src1[y];
        }
    }
    __syncthreads();

    int lane = tid & 31;
    int wi = tid >> 5;             // 0..15
    int y0 = wi << 3;              // 8 y per thread, 128 y per block

    ull a64[8] = {0,0,0,0,0,0,0,0};
    ull k2[8] = {0,0,0,0,0,0,0,0};
    const float* srow = s + y0 * SROW + lane * 2;

#pragma unroll 8
    for (int ss = 0; ss < TAPP; ss++) {
        ull d = *(const ull*)(srow + ss * SROW);
#pragma unroll
        for (int r = 7; r > 0; r--) k2[r] = k2[r - 1];
        k2[0] = skc2[ss];
#pragma unroll
        for (int r = 0; r < 8; r++) FMA_F32X2(a64[r], d, k2[r]);
    }
    __syncthreads();               // all window reads done; tb may now overwrite it

    {   // transpose to [w4][y][n] halfs in smem
        int w4a = lane >> 3, nn = lane & 7;
        __half* pa = tb + w4a * TBW + y0 * 8 + nn;
        __half* pb = tb + (w4a + 4) * TBW + y0 * 8 + nn;
#pragma unroll
        for (int r = 0; r < 8; r++) {
            float2 f = *(float2*)&a64[r];
            pa[r * 8] = __float2half_rn(f.x);
            pb[r * 8] = __float2half_rn(f.y);
        }
    }
    __syncthreads();

#pragma unroll
    for (int rr = tid; rr < 1024; rr += 512) {
        int w4 = rr >> 7, yy = rr & 127;
        uint4 v = *(uint4*)(tb + w4 * TBW + yy * 8);
        *(uint4*)(g_blend2 + ((size_t)(wtile + w4) * Hh + ytile + yy) * 8) = v;
    }
}

// ---------------- stage E: backprojection v10 — adjacent-i pairing (B<=0 always) ----
// grid (16,64)=1024 blocks, 128 threads, 8 blocks/SM. Tile 32j x 8i; thread: 1 j x
// 2 ADJACENT i x 8 batches. py(i+1)=py(i)+B, B<=0 => y(i+1)<=y(i) ALWAYS: pixel i+1
// reads (a0,a1) SEL-free; only pixel i pays 8 predicated SELs. 3 LDS.128 / 2 px kept.
#define BP_STAGES 4
#define BP_ANG 8
#define BP_ROWS 40
#define BP_ANG_BYTES (BP_ROWS * 16)                 // 640
#define BP_STAGE_U4 (BP_ANG * BP_ROWS)              // 320 uint4
#define BP_STAGE_BYTES (BP_STAGE_U4 * 16)           // 5120
#define BP_ROUNDS (Ww / BP_ANG)                     // 45
__global__ void __launch_bounds__(128, 8) backproj_kernel(float* __restrict__ out) {
    extern __shared__ __align__(16) uint4 ph[];     // 4 stages x 320 uint4 = 20480 B
    __shared__ float shA[Ww], shB[Ww], shYc[Ww];
    __shared__ int shY[Ww];
    __shared__ __align__(8) unsigned long long mbar[BP_STAGES];

    int tid = threadIdx.x;

    float jr0 = (float)((int)blockIdx.x * 32 - 256);
    float jr1 = jr0 + 31.0f;
    float ir0f = (float)((int)blockIdx.y * 8 - 256);
    float ir1f = ir0f + 7.0f;

    for (int idx = tid; idx < Ww; idx += 128) {
        float A = g_A[idx], B = g_B[idx];
        shA[idx] = A; shB[idx] = B;
        float minpy = fminf(A * jr0, A * jr1) + fminf(B * ir0f, B * ir1f) + 383.5f;
        int ylo = (int)minpy - 2;
        ylo = min(max(ylo, 0), Hh - BP_ROWS);
        shY[idx] = ylo;
        shYc[idx] = 383.5f - (float)ylo;
    }

    unsigned int mbar_base, ph_base;
    {
        unsigned long long gp = (unsigned long long)mbar;
        asm("{ .reg .u64 t; cvta.to.shared.u64 t, %1; cvt.u32.u64 %0, t; }"
            : "=r"(mbar_base) : "l"(gp));
        gp = (unsigned long long)ph;
        asm("{ .reg .u64 t; cvta.to.shared.u64 t, %1; cvt.u32.u64 %0, t; }"
            : "=r"(ph_base) : "l"(gp));
    }

    if (tid < BP_STAGES)
        asm volatile("mbarrier.init.shared.b64 [%0], %1;"
                     :: "r"(mbar_base + tid * 8), "r"(1) : "memory");
    __syncthreads();     // shY/shA/shB/shYc + mbar init visible

    const char* gsrc = (const char*)g_blend2;
    if (tid == 0) {
#pragma unroll
        for (int s = 0; s < BP_STAGES; s++) {
            unsigned int mb = mbar_base + s * 8;
            asm volatile("mbarrier.arrive.expect_tx.shared.b64 _, [%0], %1;"
                         :: "r"(mb), "r"(BP_STAGE_BYTES) : "memory");
#pragma unroll
            for (int h = 0; h < BP_ANG; h++) {
                int a = s * BP_ANG + h;
                asm volatile("cp.async.bulk.shared::cta.global.mbarrier::complete_tx::bytes "
                             "[%0], [%1], %2, [%3];"
                             :: "r"(ph_base + s * BP_STAGE_BYTES + h * BP_ANG_BYTES),
                                "l"(gsrc + ((size_t)a * Hh + shY[a]) * 16),
                                "r"(BP_ANG_BYTES), "r"(mb) : "memory");
            }
        }
    }

    int warp = tid >> 5, lane = tid & 31;
    int lj = lane & 7;                 // 8 consecutive lanes = 8 consecutive j
    int li2 = lane >> 3;               // 4 i-pairs per warp
    int j = blockIdx.x * 32 + warp * 8 + lj;
    float jr = (float)(j - 256);
    int i0 = blockIdx.y * 8 + li2 * 2;                  // this thread: pixels i0, i0+1
    float irf = (float)(i0 - 256);

    float acc[2][8] = {};
    __half2 hones = __float2half2_rn(1.0f);

    for (int rnd = 0; rnd < BP_ROUNDS; rnd++) {
        int b = rnd % BP_STAGES;
        unsigned int mb = mbar_base + b * 8;
        unsigned int parity = (unsigned int)((rnd / BP_STAGES) & 1);
        {
            unsigned int done;
            asm volatile(
                "{\n\t.reg .pred p;\n\t"
                "mbarrier.try_wait.parity.shared.b64 p, [%1], %2;\n\t"
                "selp.b32 %0, 1, 0, p;\n\t}"
                : "=r"(done) : "r"(mb), "r"(parity) : "memory");
            while (!done) {
                asm volatile(
                    "{\n\t.reg .pred p;\n\t"
                    "mbarrier.try_wait.parity.shared.b64 p, [%1], %2, 0x989680;\n\t"
                    "selp.b32 %0, 1, 0, p;\n\t}"
                    : "=r"(done) : "r"(mb), "r"(parity) : "memory");
            }
        }

        const uint4* buf = ph + b * BP_STAGE_U4;

#pragma unroll
        for (int g2 = 0; g2 < 2; g2++) {       // flush half2 partials every 4 angles
            __half2 pacc0[4], pacc1[4];
#pragma unroll
            for (int q = 0; q < 4; q++) {
                pacc0[q] = __float2half2_rn(0.0f);
                pacc1[q] = __float2half2_rn(0.0f);
            }

#pragma unroll
            for (int hh = 0; hh < 4; hh++) {
                int h = g2 * 4 + hh;
                int a = BP_ANG * rnd + h;
                float A = shA[a], B = shB[a];
                float yc = shYc[a];
                const uint4* rows = buf + h * BP_ROWS;

                float py0 = fmaf(A, jr, fmaf(B, irf, yc));   // pixel i0 (hi)
                float py1 = py0 + B;                          // pixel i0+1 (lo), B<=0
                int y0 = (int)py0;
                float wy0 = py0 - (float)y0;
                int y1 = (int)py1;
                float wy1 = py1 - (float)y1;
                int d = y0 - y1;                              // 0 or 1, ALWAYS >= 0

                uint4 r0 = rows[y1];                          // yb = y1 unconditionally
                uint4 r1 = rows[y1 + 1];
                uint4 r2 = rows[y1 + 2];

                __half2 h11 = __float2half2_rn(wy1);
                __half2 h01 = __hsub2(hones, h11);
                __half2 h10 = __float2half2_rn(wy0);
                __half2 h00 = __hsub2(hones, h10);

                const unsigned int* a0 = (const unsigned int*)&r0;
                const unsigned int* a1 = (const unsigned int*)&r1;
                const unsigned int* a2 = (const unsigned int*)&r2;
#pragma unroll
                for (int q = 0; q < 4; q++) {
                    // pixel i0+1 (lo): rows (y1, y1+1) direct — NO SEL
                    __half2 va = *(__half2*)&a0[q];
                    __half2 vb = *(__half2*)&a1[q];
                    pacc1[q] = __hfma2(va, h01, pacc1[q]);
                    pacc1[q] = __hfma2(vb, h11, pacc1[q]);
                    // pixel i0 (hi): rows (y1+d, y1+d+1) — 2 SELs
                    unsigned int pa = d ? a1[q] : a0[q];
                    unsigned int pb = d ? a2[q] : a1[q];
                    __half2 vc = *(__half2*)&pa;
                    __half2 vd = *(__half2*)&pb;
                    pacc0[q] = __hfma2(vc, h00, pacc0[q]);
                    pacc0[q] = __hfma2(vd, h10, pacc0[q]);
                }
            }
#pragma unroll
            for (int q = 0; q < 4; q++) {
                float2 f0 = __half22float2(pacc0[q]);
                float2 f1 = __half22float2(pacc1[q]);
                acc[0][2 * q]     += f0.x;
                acc[0][2 * q + 1] += f0.y;
                acc[1][2 * q]     += f1.x;
                acc[1][2 * q + 1] += f1.y;
            }
        }

        __syncthreads();            // all readers of stage b done
        if (tid == 0 && rnd + BP_STAGES < BP_ROUNDS) {
            asm volatile("mbarrier.arrive.expect_tx.shared.b64 _, [%0], %1;"
                         :: "r"(mb), "r"(BP_STAGE_BYTES) : "memory");
#pragma unroll
            for (int h = 0; h < BP_ANG; h++) {
                int a = (rnd + BP_STAGES) * BP_ANG + h;
                asm volatile("cp.async.bulk.shared::cta.global.mbarrier::complete_tx::bytes "
                             "[%0], [%1], %2, [%3];"
                             :: "r"(ph_base + b * BP_STAGE_BYTES + h * BP_ANG_BYTES),
                                "l"(gsrc + ((size_t)a * Hh + shY[a]) * 16),
                                "r"(BP_ANG_BYTES), "r"(mb) : "memory");
            }
        }
    }

    const float SC = (float)(PI_D / 720.0);   // pi / (2W)
#pragma unroll
    for (int p = 0; p < 2; p++) {
#pragma unroll
        for (int n = 0; n < 8; n++)
            out[n * (Dd * Dd) + (i0 + p) * Dd + j] = acc[p][n] * SC;
    }
}

// ---------------- launch ----------------
extern "C" void kernel_launch(void* const* d_in, const int* in_sizes, int n_in,
                              void* d_out, int out_size) {
    (void)in_sizes; (void)n_in; (void)out_size;
    const float* radon = (const float*)d_in[0];
    const float* hG    = (const float*)d_in[1];
    float* out = (float*)d_out;

    const int conv_smem = WIN * SROW * 4 + TAPP * 8;              // 79,552 B
    cudaFuncSetAttribute(conv_kernel, cudaFuncAttributeMaxDynamicSharedMemorySize, conv_smem);
    const int bp_smem = BP_STAGES * BP_STAGE_BYTES;                // 20,480 B
    cudaFuncSetAttribute(backproj_kernel, cudaFuncAttributeMaxDynamicSharedMemorySize, bp_smem);

    compute_kcp_kernel<<<TAPP, 256>>>(hG);
    params_kernel<<<1, 384>>>();
    rb_kernel<<<dim3(24, 8), 256>>>(radon);
    conv_kernel<<<dim3(45, 6), 512, conv_smem>>>();
    backproj_kernel<<<dim3(16, 64), 128, bp_smem>>>(out);
}

// round 17
// speedup vs baseline: 1.2133x; 1.0395x over previous
#include <cuda_runtime.h>
#include <cuda_fp16.h>

#define Nn 8
#define Hh 768
#define Ww 360
#define Dd 512
#define Cc (Ww*Nn)          // 2880 columns, c = w*8 + n
#define TAPS 169            // band: |d| <= 84
#define TAPP 176            // padded to multiple of 8
#define KOFF 84
#define PI_D 3.14159265358979323846
typedef unsigned long long ull;

// ---------------- scratch (no allocation allowed) ----------------
__device__ float g_kcp[TAPP];                // kcp[s] = k_signed(s-84), zero-padded
__device__ float g_Rb[Cc*Hh];                // x-blended radon columns, [c][y]
__device__ __align__(16) __half g_blend2[(size_t)Ww*Hh*Nn];  // filtered, [w][y][n] fp16
__device__ float g_A[Ww], g_B[Ww];
__device__ int   g_x0[Ww], g_x1[Ww];
__device__ float g_w0[Ww], g_w1[Ww];

// packed fp32x2 FMA (Blackwell)
#define FMA_F32X2(acc, d, k) asm("fma.rn.f32x2 %0, %1, %2, %0;" : "+l"(acc) : "l"(d), "l"(k))

// ---------------- stage A: taps (blocks 0..TAPP-1) + per-angle params (block TAPP) ----------
__global__ void compute_kcp_kernel(const float* __restrict__ hG) {
    int m = blockIdx.x;
    int t = threadIdx.x;
    if (m == TAPP) {                 // fused params block
        for (int w = t; w < Ww; w += 256) {
            float thf = __double2float_rn(PI_D / 180.0) * (0.5f * (float)w);
            double c = cos((double)thf), s = sin((double)thf);
            double sc = 383.5 / 384.0;
            g_A[w] = (float)(c * sc);
            g_B[w] = (float)(-s * sc);
            float step = __double2float_rn(2.0 / 359.0);
            float tx = -1.0f + (float)w * step;
            float px = (tx + 1.0f) * 179.5f;
            float x0f = floorf(px);
            float wx = px - x0f;
            int ix0 = (int)x0f, ix1 = ix0 + 1;
            float v0 = (ix0 >= 0 && ix0 < Ww) ? 1.0f : 0.0f;
            float v1 = (ix1 >= 0 && ix1 < Ww) ? 1.0f : 0.0f;
            g_w0[w] = (1.0f - wx) * v0;
            g_w1[w] = wx * v1;
            g_x0[w] = min(max(ix0, 0), Ww - 1);
            g_x1[w] = min(max(ix1, 0), Ww - 1);
        }
        return;
    }
    double acc = 0.0;
    if (m < TAPS) {
        double dd = (double)(m - KOFF);
        double ang = 2.0 * PI_D * dd / (double)Hh;
        for (int u = t; u < Hh; u += 256)
            acc += (double)hG[u] * cos(ang * (double)u);
    }
    __shared__ double red[256];
    red[t] = acc;
    __syncthreads();
    for (int s = 128; s > 0; s >>= 1) {
        if (t < s) red[t] += red[t + s];
        __syncthreads();
    }
    if (t == 0) g_kcp[m] = (m < TAPS) ? (float)(red[0] / (double)Hh) : 0.0f;
}

// ---------------- stage C: x-blend, smem-tiled (coalesced in AND out) ----------------
__global__ void __launch_bounds__(256) rb_kernel(const float* __restrict__ radon) {
    __shared__ float sm[32 * 361];     // stride 361: conflict-free
    int n = blockIdx.y;
    int yt = blockIdx.x * 32;
    int tid = threadIdx.x;
    const float* src = radon + ((size_t)n * Hh + yt) * Ww;
#pragma unroll
    for (int idx = tid; idx < 32 * Ww; idx += 256) {
        int y = idx / Ww, x = idx - y * Ww;
        sm[y * 361 + x] = src[y * Ww + x];
    }
    __syncthreads();
#pragma unroll
    for (int idx = tid; idx < Ww * 32; idx += 256) {
        int w = idx >> 5, y = idx & 31;
        float v = sm[y * 361 + g_x0[w]] * g_w0[w] + sm[y * 361 + g_x1[w]] * g_w1[w];
        g_Rb[(size_t)(w * 8 + n) * Hh + yt + y] = v;
    }
}

// ---------------- stage D: 169-tap band conv, one-wave tiling (64c x 128y, 512 thr) ----
#define SROW 66                     // words per row (32 float2 + 1 pad float2)
#define WIN 304                     // window rows: >=296 needed; 304 = 19*16 (uniform trips)
#define TBW 1040                    // halfs per w4 slice: 128*8 + 16 pad
__global__ void __launch_bounds__(512, 2) conv_kernel() {
    extern __shared__ float dyn[];
    float* s = dyn;                          // 304*66 words = 80256 B (window)
    ull* skc2 = (ull*)(dyn + WIN * SROW);    // 176 dup'd tap pairs = 1408 B
    __half* tb = (__half*)dyn;               // transpose buf ALIASES window (post-sync)

    int tid = threadIdx.x;
    int ctile = blockIdx.x * 64;
    int wtile = blockIdx.x * 8;
    int ytile = blockIdx.y * 128;

    for (int i = tid; i < TAPP; i += 512) {
        unsigned int ki = __float_as_uint(g_kcp[i]);
        ull kn;
        asm("mov.b64 %0, {%1, %1};" : "=l"(kn) : "r"(ki));
        skc2[i] = kn;
    }

    {   // load window (circular wrap): 304 rows x 32 col-pairs, 19 trips/thread
        int cloc = tid >> 4;          // 0..31
        int uoff = tid & 15;
        const float* src0 = g_Rb + (ctile + cloc) * Hh;
        const float* src1 = g_Rb + (ctile + 32 + cloc) * Hh;
#pragma unroll
        for (int u = uoff; u < WIN; u += 16) {
            int y = ytile + u - KOFF;
            if (y < 0) y += Hh; else if (y >= Hh) y -= Hh;
            s[u * SROW + cloc * 2]     = src0[y];
            s[u * SROW + cloc * 2 + 1] = src1[y];
        }
    }
    __syncthreads();

    int lane = tid & 31;
    int wi = tid >> 5;             // 0..15
    int y0 = wi << 3;              // 8 y per thread, 128 y per block

    ull a64[8] = {0,0,0,0,0,0,0,0};
    ull k2[8] = {0,0,0,0,0,0,0,0};
    const float* srow = s + y0 * SROW + lane * 2;

#pragma unroll 8
    for (int ss = 0; ss < TAPP; ss++) {
        ull d = *(const ull*)(srow + ss * SROW);
#pragma unroll
        for (int r = 7; r > 0; r--) k2[r] = k2[r - 1];
        k2[0] = skc2[ss];
#pragma unroll
        for (int r = 0; r < 8; r++) FMA_F32X2(a64[r], d, k2[r]);
    }
    __syncthreads();               // all window reads done; tb may now overwrite it

    {   // transpose to [w4][y][n] halfs in smem
        int w4a = lane >> 3, nn = lane & 7;
        __half* pa = tb + w4a * TBW + y0 * 8 + nn;
        __half* pb = tb + (w4a + 4) * TBW + y0 * 8 + nn;
#pragma unroll
        for (int r = 0; r < 8; r++) {
            float2 f = *(float2*)&a64[r];
            pa[r * 8] = __float2half_rn(f.x);
            pb[r * 8] = __float2half_rn(f.y);
        }
    }
    __syncthreads();

#pragma unroll
    for (int rr = tid; rr < 1024; rr += 512) {
        int w4 = rr >> 7, yy = rr & 127;
        uint4 v = *(uint4*)(tb + w4 * TBW + yy * 8);
        *(uint4*)(g_blend2 + ((size_t)(wtile + w4) * Hh + ytile + yy) * 8) = v;
    }
}

// ---------------- stage E: backprojection v11 — 3-coeff SEL-free q-loop ----
// grid (16,64)=1024 blocks, 128 threads, 8 blocks/SM. Tile 32j x 8i; thread: 1 j x
// 2 ADJACENT i x 8 batches. B<=0 => yb=y1 always; hi pixel = sum of 3 rows with coeffs
// (d?0:1-w, d?1-w:w, d?w:0) -> q-loop is pure HFMA2, zero SELs (bit-identical numerics).
#define BP_STAGES 4
#define BP_ANG 8
#define BP_ROWS 40
#define BP_ANG_BYTES (BP_ROWS * 16)                 // 640
#define BP_STAGE_U4 (BP_ANG * BP_ROWS)              // 320 uint4
#define BP_STAGE_BYTES (BP_STAGE_U4 * 16)           // 5120
#define BP_ROUNDS (Ww / BP_ANG)                     // 45
__global__ void __launch_bounds__(128, 8) backproj_kernel(float* __restrict__ out) {
    extern __shared__ __align__(16) uint4 ph[];     // 4 stages x 320 uint4 = 20480 B
    __shared__ float shA[Ww], shB[Ww], shYc[Ww];
    __shared__ int shY[Ww];
    __shared__ __align__(8) unsigned long long mbar[BP_STAGES];

    int tid = threadIdx.x;

    float jr0 = (float)((int)blockIdx.x * 32 - 256);
    float jr1 = jr0 + 31.0f;
    float ir0f = (float)((int)blockIdx.y * 8 - 256);
    float ir1f = ir0f + 7.0f;

    for (int idx = tid; idx < Ww; idx += 128) {
        float A = g_A[idx], B = g_B[idx];
        shA[idx] = A; shB[idx] = B;
        float minpy = fminf(A * jr0, A * jr1) + fminf(B * ir0f, B * ir1f) + 383.5f;
        int ylo = (int)minpy - 2;
        ylo = min(max(ylo, 0), Hh - BP_ROWS);
        shY[idx] = ylo;
        shYc[idx] = 383.5f - (float)ylo;
    }

    unsigned int mbar_base, ph_base;
    {
        unsigned long long gp = (unsigned long long)mbar;
        asm("{ .reg .u64 t; cvta.to.shared.u64 t, %1; cvt.u32.u64 %0, t; }"
            : "=r"(mbar_base) : "l"(gp));
        gp = (unsigned long long)ph;
        asm("{ .reg .u64 t; cvta.to.shared.u64 t, %1; cvt.u32.u64 %0, t; }"
            : "=r"(ph_base) : "l"(gp));
    }

    if (tid < BP_STAGES)
        asm volatile("mbarrier.init.shared.b64 [%0], %1;"
                     :: "r"(mbar_base + tid * 8), "r"(1) : "memory");
    __syncthreads();     // shY/shA/shB/shYc + mbar init visible

    const char* gsrc = (const char*)g_blend2;
    if (tid == 0) {
#pragma unroll
        for (int s = 0; s < BP_STAGES; s++) {
            unsigned int mb = mbar_base + s * 8;
            asm volatile("mbarrier.arrive.expect_tx.shared.b64 _, [%0], %1;"
                         :: "r"(mb), "r"(BP_STAGE_BYTES) : "memory");
#pragma unroll
            for (int h = 0; h < BP_ANG; h++) {
                int a = s * BP_ANG + h;
                asm volatile("cp.async.bulk.shared::cta.global.mbarrier::complete_tx::bytes "
                             "[%0], [%1], %2, [%3];"
                             :: "r"(ph_base + s * BP_STAGE_BYTES + h * BP_ANG_BYTES),
                                "l"(gsrc + ((size_t)a * Hh + shY[a]) * 16),
                                "r"(BP_ANG_BYTES), "r"(mb) : "memory");
            }
        }
    }

    int warp = tid >> 5, lane = tid & 31;
    int lj = lane & 7;                 // 8 consecutive lanes = 8 consecutive j
    int li2 = lane >> 3;               // 4 i-pairs per warp
    int j = blockIdx.x * 32 + warp * 8 + lj;
    float jr = (float)(j - 256);
    int i0 = blockIdx.y * 8 + li2 * 2;                  // this thread: pixels i0, i0+1
    float irf = (float)(i0 - 256);

    float acc[2][8] = {};
    __half2 hones = __float2half2_rn(1.0f);

    for (int rnd = 0; rnd < BP_ROUNDS; rnd++) {
        int b = rnd % BP_STAGES;
        unsigned int mb = mbar_base + b * 8;
        unsigned int parity = (unsigned int)((rnd / BP_STAGES) & 1);
        {
            unsigned int done;
            asm volatile(
                "{\n\t.reg .pred p;\n\t"
                "mbarrier.try_wait.parity.shared.b64 p, [%1], %2;\n\t"
                "selp.b32 %0, 1, 0, p;\n\t}"
                : "=r"(done) : "r"(mb), "r"(parity) : "memory");
            while (!done) {
                asm volatile(
                    "{\n\t.reg .pred p;\n\t"
                    "mbarrier.try_wait.parity.shared.b64 p, [%1], %2, 0x989680;\n\t"
                    "selp.b32 %0, 1, 0, p;\n\t}"
                    : "=r"(done) : "r"(mb), "r"(parity) : "memory");
            }
        }

        const uint4* buf = ph + b * BP_STAGE_U4;

#pragma unroll
        for (int g2 = 0; g2 < 2; g2++) {       // flush half2 partials every 4 angles
            __half2 pacc0[4], pacc1[4];
#pragma unroll
            for (int q = 0; q < 4; q++) {
                pacc0[q] = __float2half2_rn(0.0f);
                pacc1[q] = __float2half2_rn(0.0f);
            }

#pragma unroll
            for (int hh = 0; hh < 4; hh++) {
                int h = g2 * 4 + hh;
                int a = BP_ANG * rnd + h;
                float A = shA[a], B = shB[a];
                float yc = shYc[a];
                const uint4* rows = buf + h * BP_ROWS;

                float py0 = fmaf(A, jr, fmaf(B, irf, yc));   // pixel i0 (hi)
                float py1 = py0 + B;                          // pixel i0+1 (lo), B<=0
                int y0 = (int)py0;
                float wy0 = py0 - (float)y0;
                int y1 = (int)py1;
                float wy1 = py1 - (float)y1;
                int d = y0 - y1;                              // 0 or 1, ALWAYS >= 0

                uint4 r0 = rows[y1];                          // yb = y1 unconditionally
                uint4 r1 = rows[y1 + 1];
                uint4 r2 = rows[y1 + 2];

                // lo pixel weights
                __half2 h11 = __float2half2_rn(wy1);
                __half2 h01 = __hsub2(hones, h11);
                // hi pixel 3-row coefficients (exactly one of c0/c2 is zero)
                float omwy0 = 1.0f - wy0;
                float c0f = d ? 0.0f : omwy0;
                float c1f = d ? omwy0 : wy0;
                float c2f = d ? wy0 : 0.0f;
                __half2 hc0 = __float2half2_rn(c0f);
                __half2 hc1 = __float2half2_rn(c1f);
                __half2 hc2 = __float2half2_rn(c2f);

                const unsigned int* a0 = (const unsigned int*)&r0;
                const unsigned int* a1 = (const unsigned int*)&r1;
                const unsigned int* a2 = (const unsigned int*)&r2;
#pragma unroll
                for (int q = 0; q < 4; q++) {
                    __half2 va = *(__half2*)&a0[q];
                    __half2 vb = *(__half2*)&a1[q];
                    __half2 vc = *(__half2*)&a2[q];
                    // pixel i0+1 (lo): rows (y1, y1+1) direct
                    pacc1[q] = __hfma2(va, h01, pacc1[q]);
                    pacc1[q] = __hfma2(vb, h11, pacc1[q]);
                    // pixel i0 (hi): 3-coeff, SEL-free
                    pacc0[q] = __hfma2(va, hc0, pacc0[q]);
                    pacc0[q] = __hfma2(vb, hc1, pacc0[q]);
                    pacc0[q] = __hfma2(vc, hc2, pacc0[q]);
                }
            }
#pragma unroll
            for (int q = 0; q < 4; q++) {
                float2 f0 = __half22float2(pacc0[q]);
                float2 f1 = __half22float2(pacc1[q]);
                acc[0][2 * q]     += f0.x;
                acc[0][2 * q + 1] += f0.y;
                acc[1][2 * q]     += f1.x;
                acc[1][2 * q + 1] += f1.y;
            }
        }

        __syncthreads();            // all readers of stage b done
        if (tid == 0 && rnd + BP_STAGES < BP_ROUNDS) {
            asm volatile("mbarrier.arrive.expect_tx.shared.b64 _, [%0], %1;"
                         :: "r"(mb), "r"(BP_STAGE_BYTES) : "memory");
#pragma unroll
            for (int h = 0; h < BP_ANG; h++) {
                int a = (rnd + BP_STAGES) * BP_ANG + h;
                asm volatile("cp.async.bulk.shared::cta.global.mbarrier::complete_tx::bytes "
                             "[%0], [%1], %2, [%3];"
                             :: "r"(ph_base + b * BP_STAGE_BYTES + h * BP_ANG_BYTES),
                                "l"(gsrc + ((size_t)a * Hh + shY[a]) * 16),
                                "r"(BP_ANG_BYTES), "r"(mb) : "memory");
            }
        }
    }

    const float SC = (float)(PI_D / 720.0);   // pi / (2W)
#pragma unroll
    for (int p = 0; p < 2; p++) {
#pragma unroll
        for (int n = 0; n < 8; n++)
            out[n * (Dd * Dd) + (i0 + p) * Dd + j] = acc[p][n] * SC;
    }
}

// ---------------- launch ----------------
extern "C" void kernel_launch(void* const* d_in, const int* in_sizes, int n_in,
                              void* d_out, int out_size) {
    (void)in_sizes; (void)n_in; (void)out_size;
    const float* radon = (const float*)d_in[0];
    const float* hG    = (const float*)d_in[1];
    float* out = (float*)d_out;

    const int conv_smem = WIN * SROW * 4 + TAPP * 8;              // 81,664 B
    cudaFuncSetAttribute(conv_kernel, cudaFuncAttributeMaxDynamicSharedMemorySize, conv_smem);
    const int bp_smem = BP_STAGES * BP_STAGE_BYTES;                // 20,480 B
    cudaFuncSetAttribute(backproj_kernel, cudaFuncAttributeMaxDynamicSharedMemorySize, bp_smem);

    compute_kcp_kernel<<<TAPP + 1, 256>>>(hG);   // taps + fused params
    rb_kernel<<<dim3(24, 8), 256>>>(radon);
    conv_kernel<<<dim3(45, 6), 512, conv_smem>>>();
    backproj_kernel<<<dim3(16, 64), 128, bp_smem>>>(out);
}